// round 6
// baseline (speedup 1.0000x reference)
#include <cuda_runtime.h>

// HybridQuanvolutionFraudNet — exact constant folding (see R0 notes):
// log_softmax over a singleton axis is bitwise 0.0f for every sample; the
// whole quanvolution+MLP pipeline is dead code. Output = 2048 zeros.
//
// R4: minimize per-warp launch/drain overhead. 4 warps instead of 16; each
// thread issues 4 unrolled STG.128 (stores are issue-only, ~4-cyc structural
// floor apart), total 16 STG.128 warp-instructions — same as R3 but with
// 12 fewer warps to initialize and drain.

__global__ __launch_bounds__(128, 1)
void hqfn_zero_vec4x4_kernel(float4* __restrict__ out) {
    const float4 z = make_float4(0.f, 0.f, 0.f, 0.f);
    const unsigned t = threadIdx.x;
#pragma unroll
    for (int k = 0; k < 4; ++k) {
        // float4 index: 512 total = 4 chunks of 128; coalesced per warp.
        out[t + k * 128] = z;
    }
}

// Generic fallback for arbitrary out_size (not taken for this problem's
// fixed 2048-element output, but keeps kernel_launch shape-safe).
__global__ void hqfn_zero_scalar_kernel(float* __restrict__ out, int n) {
    int i = blockIdx.x * blockDim.x + threadIdx.x;
    if (i < n) out[i] = 0.0f;
}

extern "C" void kernel_launch(void* const* d_in, const int* in_sizes, int n_in,
                              void* d_out, int out_size) {
    (void)d_in; (void)in_sizes; (void)n_in;
    if (out_size == 2048) {
        hqfn_zero_vec4x4_kernel<<<1, 128>>>((float4*)d_out);
    } else {
        int threads = 256;
        int blocks = (out_size + threads - 1) / threads;
        hqfn_zero_scalar_kernel<<<blocks, threads>>>((float*)d_out, out_size);
    }
}